// round 12
// baseline (speedup 1.0000x reference)
#include <cuda_runtime.h>
#include <cuda_fp16.h>
#include <stdint.h>

#define N_NODES 50000
#define N_EDGES 625000
#define IN_DIMS 128

#define GRID 148
#define THREADS 1024
#define WARPS (THREADS / 32)                                  // 32
#define TOTAL_WARPS (GRID * WARPS)                            // 4736
#define ROWS_PER_WARP ((N_NODES + TOTAL_WARPS - 1) / TOTAL_WARPS)  // 11
#define NODE_BATCH 4

// Per-CTA edge chunk, rounded UP TO EVEN so every int2/float2 access stays
// 8-byte aligned (odd chunk was the R11 misaligned-address trap).
#define EDGE_CHUNK_RAW ((N_EDGES + GRID - 1) / GRID)          // 4223 (odd!)
#define EDGE_CHUNK ((EDGE_CHUNK_RAW + 1) & ~1)                // 4224 (even)
#define EDGE_ITERS ((EDGE_CHUNK + THREADS * 2 - 1) / (THREADS * 2))  // 3
#define TABLE_BYTES (N_NODES * 4)                             // 200000 B (half2/node)

// Interleaved per-node table: {s = x.W_src + b, t = x.W_dst} as fp16.
__device__ __align__(16) __half2 g_st[N_NODES];
// Grid barrier counter: monotonic across graph replays (epoch arithmetic),
// never reset -> deterministic work, output-invariant.
__device__ unsigned g_bar = 0;

__global__ void __launch_bounds__(THREADS, 1)
fused_kernel(const float* __restrict__ x,
             const int* __restrict__ ei,
             const float* __restrict__ W,
             const float* __restrict__ b,
             float* __restrict__ out) {
    extern __shared__ __half2 st[];
    int tid  = threadIdx.x;
    int wid  = tid >> 5;
    int lane = tid & 31;
    int gw   = (int)blockIdx.x * WARPS + wid;     // global warp id

    // ---- Phase 0: prefetch this thread's edge indices (overlaps node phase) ----
    int ebase = (int)blockIdx.x * EDGE_CHUNK;     // even -> int2/float2 aligned
    int eend  = min(ebase + EDGE_CHUNK, N_EDGES);
    int2 si[EDGE_ITERS], di[EDGE_ITERS];
    #pragma unroll
    for (int i = 0; i < EDGE_ITERS; i++) {
        int e = ebase + (i * THREADS + tid) * 2;
        if (e < eend) {
            si[i] = *reinterpret_cast<const int2*>(ei + e);
            di[i] = *reinterpret_cast<const int2*>(ei + N_EDGES + e);
        } else {
            si[i] = make_int2(0, 0);
            di[i] = make_int2(0, 0);
        }
    }

    // ---- Phase 1: node slice — warp gw computes rows [gw*RPW, gw*RPW+RPW) ----
    {
        const float4 ws = reinterpret_cast<const float4*>(W)[lane];             // W_src
        const float4 wd = reinterpret_cast<const float4*>(W + IN_DIMS)[lane];   // W_dst
        float bias = __ldg(b);
        int row_base = gw * ROWS_PER_WARP;

        #pragma unroll
        for (int bb = 0; bb < ROWS_PER_WARP; bb += NODE_BATCH) {
            int rb = row_base + bb;
            if (rb >= N_NODES) break;
            int nb = min(NODE_BATCH, ROWS_PER_WARP - bb);

            float4 xa[NODE_BATCH];
            #pragma unroll
            for (int r = 0; r < NODE_BATCH; r++) {
                int row = rb + r;
                if (r < nb && row < N_NODES)
                    xa[r] = reinterpret_cast<const float4*>(x + (size_t)row * IN_DIMS)[lane];
            }

            __half2 mine = make_half2(__float2half_rn(0.f), __float2half_rn(0.f));
            #pragma unroll
            for (int r = 0; r < NODE_BATCH; r++) {
                int row = rb + r;
                if (r >= nb || row >= N_NODES) break;
                float ps = fmaf(xa[r].x, ws.x, fmaf(xa[r].y, ws.y, fmaf(xa[r].z, ws.z, xa[r].w * ws.w)));
                float pt = fmaf(xa[r].x, wd.x, fmaf(xa[r].y, wd.y, fmaf(xa[r].z, wd.z, xa[r].w * wd.w)));
                #pragma unroll
                for (int o = 16; o > 0; o >>= 1) {
                    ps += __shfl_xor_sync(0xffffffffu, ps, o);   // result in all lanes
                    pt += __shfl_xor_sync(0xffffffffu, pt, o);
                }
                if (lane == r)
                    mine = make_half2(__float2half_rn(ps + bias), __float2half_rn(pt));
            }
            // Coalesced store: lanes 0..nb-1 write consecutive half2.
            if (lane < nb && rb + lane < N_NODES)
                g_st[rb + lane] = mine;
        }
    }

    // ---- Grid barrier (monotonic epoch; all 148 CTAs are resident) ----
    __threadfence();
    __syncthreads();
    if (tid == 0) {
        unsigned old = atomicAdd(&g_bar, 1u);
        unsigned target = (old / GRID + 1u) * GRID;   // end of this replay's round
        while (atomicAdd(&g_bar, 0u) < target) { }
    }
    __syncthreads();

    // ---- Phase 2: stage full table in smem (cp.async; table is L2-hot) ----
    uint32_t s_base;
    asm("{ .reg .u64 t; cvta.to.shared.u64 t, %1; cvt.u32.u64 %0, t; }"
        : "=r"(s_base) : "l"(st));
    {
        const char* g_base = reinterpret_cast<const char*>(g_st);
        const int n_chunks = TABLE_BYTES / 16;   // 12500
        #pragma unroll 4
        for (int c = tid; c < n_chunks; c += THREADS) {
            asm volatile("cp.async.cg.shared.global [%0], [%1], 16;"
                         :: "r"(s_base + c * 16), "l"(g_base + (size_t)c * 16));
        }
        asm volatile("cp.async.commit_group;");
        asm volatile("cp.async.wait_group 0;" ::: "memory");
    }
    __syncthreads();

    // ---- Phase 3: gather from smem, compute, store (bias folded in table) ----
    #pragma unroll
    for (int i = 0; i < EDGE_ITERS; i++) {
        int e = ebase + (i * THREADS + tid) * 2;
        if (e < eend) {
            __half2 a0 = st[si[i].x];
            __half2 c0 = st[di[i].x];
            __half2 a1 = st[si[i].y];
            __half2 c1 = st[di[i].y];
            float2 r;
            r.x = __low2float(a0) + __high2float(c0);
            r.y = __low2float(a1) + __high2float(c1);
            *reinterpret_cast<float2*>(out + e) = r;
        }
    }
}

extern "C" void kernel_launch(void* const* d_in, const int* in_sizes, int n_in,
                              void* d_out, int out_size) {
    const float* x   = (const float*)d_in[0];   // [N_NODES, 128] f32
    const int*   ei  = (const int*)d_in[1];     // [2, N_EDGES] int32
    const float* W   = (const float*)d_in[2];   // [1, 256] f32
    const float* b   = (const float*)d_in[3];   // [1] f32
    float*       out = (float*)d_out;           // [N_EDGES] f32

    // Host-side config (not a stream op); idempotent.
    cudaFuncSetAttribute(fused_kernel,
                         cudaFuncAttributeMaxDynamicSharedMemorySize, TABLE_BYTES);

    fused_kernel<<<GRID, THREADS, TABLE_BYTES>>>(x, ei, W, b, out);
}